// round 15
// baseline (speedup 1.0000x reference)
#include <cuda_runtime.h>
#include <cstdint>

#define KDIM 7168
#define ODIM 16384
#define MDIM 32
#define OTILE 64
#define KTILE 64
#define NKT_TOTAL (KDIM / KTILE)       /* 112 */
#define KSPLIT 2
#define NKT_HALF (NKT_TOTAL / KSPLIT)  /* 56 tiles per CTA */
#define NSC  56                 /* scale cols (128-wide k blocks) */
#define NTHREADS 160            /* warps 0-3 consumers, warp 4 producer */
#define STRIDE 68               /* 64+4 pad; conflict-free fragment LDS */
#define W_STAGE_F (OTILE * STRIDE)   /* 4352 floats = 17,408 B */
#define X_STAGE_F (MDIM * STRIDE)    /* 2176 floats =  8,704 B */
#define NSTAGE 4

#define RING_BYTES (NSTAGE * (W_STAGE_F + X_STAGE_F) * 4)   /* 104,448 */
#define SMEM_BYTES (RING_BYTES + 64 + 16)                   /* + mbarriers + flag */

__device__ uint32_t g_xtf[MDIM * KDIM];              // pre-rounded tf32 x
__device__ float    g_part[KSPLIT * MDIM * ODIM];    // k-split partials (4 MB)
__device__ int      g_ticket[ODIM / OTILE];          // per-o-block arrivals (zero-init)

__device__ __forceinline__ uint32_t smem_u32(const void* p) {
    uint32_t a;
    asm("{ .reg .u64 t; cvta.to.shared.u64 t, %1; cvt.u32.u64 %0, t; }" : "=r"(a) : "l"(p));
    return a;
}

__device__ __forceinline__ uint32_t tf32r(float v) { // fp32 -> tf32 round-to-nearest
    uint32_t u;
    asm("cvt.rna.tf32.f32 %0, %1;" : "=r"(u) : "f"(v));
    return u;
}

__device__ __forceinline__ float ldcg(const float* p) {
    float v;
    asm volatile("ld.global.cg.f32 %0, [%1];" : "=f"(v) : "l"(p));
    return v;
}

__device__ __forceinline__ void cp_async16(uint32_t dst_smem, const void* src) {
    asm volatile("cp.async.cg.shared.global [%0], [%1], 16;" :: "r"(dst_smem), "l"(src) : "memory");
}
#define CP_COMMIT() asm volatile("cp.async.commit_group;" ::: "memory")
#define CP_WAIT2()  asm volatile("cp.async.wait_group 2;" ::: "memory")
#define CP_WAIT1()  asm volatile("cp.async.wait_group 1;" ::: "memory")
#define CP_WAIT0()  asm volatile("cp.async.wait_group 0;" ::: "memory")

#define MBAR_INIT(addr, cnt) \
    asm volatile("mbarrier.init.shared.b64 [%0], %1;" :: "r"((uint32_t)(addr)), "r"((uint32_t)(cnt)) : "memory")
#define MBAR_ARRIVE(addr) \
    asm volatile("mbarrier.arrive.shared.b64 _, [%0];" :: "r"((uint32_t)(addr)) : "memory")

#define MBAR_WAIT(mbar_addr, phase_parity) do {                                              \
    uint32_t _mbar = (uint32_t)(mbar_addr);                                                  \
    uint32_t _par  = (uint32_t)(phase_parity);                                               \
    uint32_t _done;                                                                          \
    asm volatile("{\n\t.reg .pred p;\n\t"                                                    \
        "mbarrier.try_wait.parity.acquire.cta.shared::cta.b64 p, [%1], %2;\n\t"              \
        "selp.b32 %0, 1, 0, p;\n\t}"                                                         \
        : "=r"(_done) : "r"(_mbar), "r"(_par) : "memory");                                   \
    if (!_done) {                                                                            \
        asm volatile("{\n\t.reg .pred P1;\n\t"                                               \
            "WAIT_LOOP_%=:\n\t"                                                              \
            "mbarrier.try_wait.parity.acquire.cta.shared::cta.b64 P1, [%0], %1, 0x989680;\n\t" \
            "@P1 bra.uni WAIT_DONE_%=;\n\t"                                                  \
            "bra.uni WAIT_LOOP_%=;\n\t"                                                      \
            "WAIT_DONE_%=:\n\t}"                                                             \
            :: "r"(_mbar), "r"(_par) : "memory");                                            \
    }                                                                                        \
} while (0)

#define MMA_TF32(acc, a0, a1, a2, a3, b0, b1)                                  \
    asm volatile(                                                              \
        "mma.sync.aligned.m16n8k8.row.col.f32.tf32.tf32.f32 "                  \
        "{%0,%1,%2,%3}, {%4,%5,%6,%7}, {%8,%9}, {%0,%1,%2,%3};"                \
        : "+f"((acc)[0]), "+f"((acc)[1]), "+f"((acc)[2]), "+f"((acc)[3])       \
        : "r"(a0), "r"(a1), "r"(a2), "r"(a3), "r"(b0), "r"(b1))

// ---- prologue: round x to tf32 once ----
__global__ void round_x_kernel(const float* __restrict__ X) {
    int i = blockIdx.x * blockDim.x + threadIdx.x;
    if (i < MDIM * KDIM) g_xtf[i] = tf32r(X[i]);
}

__global__ __launch_bounds__(NTHREADS, 2)
void linear_tf32_mma(const float* __restrict__ W, const float* __restrict__ S,
                     float* __restrict__ out)
{
    extern __shared__ float smem[];
    float*    wbuf = smem;                                   // 4 W stages
    uint32_t* xbuf = reinterpret_cast<uint32_t*>(smem + NSTAGE * W_STAGE_F);

    const int tid  = threadIdx.x;
    const int lane = tid & 31;
    const int w    = tid >> 5;          // 0..4
    const int ob   = blockIdx.x >> 1;   // o-block (0..255)
    const int kh   = blockIdx.x & 1;    // k-half (0,1)
    const int o_base = ob * OTILE;
    const int srow = ob >> 1;           // scale blocks are 128 o-rows
    const int kt0  = kh * NKT_HALF;

    const uint32_t sbase = smem_u32(smem);
    const uint32_t wsm   = sbase;
    const uint32_t xsm   = sbase + NSTAGE * W_STAGE_F * 4;
    const uint32_t barb  = sbase + RING_BYTES;   // full[s] @ s*16, empty[s] @ s*16+8
    int* sflag = reinterpret_cast<int*>(smem) + (RING_BYTES + 64) / 4;

    if (tid == 0) {
        #pragma unroll
        for (int s = 0; s < NSTAGE; s++) {
            MBAR_INIT(barb + s * 16,     1);   // full: 1 producer arrival
            MBAR_INIT(barb + s * 16 + 8, 4);   // empty: 4 consumer-warp arrivals
        }
    }
    __syncthreads();

    float acc[2][4][4];
    #pragma unroll
    for (int b = 0; b < 2; b++)
        #pragma unroll
        for (int i = 0; i < 4; i++)
            #pragma unroll
            for (int j = 0; j < 4; j++) acc[b][i][j] = 0.0f;

    if (w == 4) {
        // ================= PRODUCER =================
        const int r0  = lane >> 4;      // 0 or 1
        const int col = lane & 15;
        const float*    gwb = W + (size_t)o_base * KDIM + (size_t)kt0 * KTILE
                                + (size_t)r0 * KDIM + (size_t)col * 4;
        const uint32_t* gxb = g_xtf + (size_t)kt0 * KTILE
                                + (size_t)r0 * KDIM + (size_t)col * 4;
        const uint32_t soff = (uint32_t)(r0 * STRIDE + col * 4) * 4u;

        #pragma unroll 1
        for (int it = 0; it < NKT_HALF; it++) {
            const int s = it & 3;
            const int eph = (((it >> 2) & 1) ^ 1);   // producer empty-phase starts at 1
            MBAR_WAIT(barb + s * 16 + 8, eph);

            const uint32_t wd = wsm + (uint32_t)s * (W_STAGE_F * 4) + soff;
            const uint32_t xd = xsm + (uint32_t)s * (X_STAGE_F * 4) + soff;
            const float*    gw = gwb + (size_t)it * KTILE;
            const uint32_t* gx = gxb + (size_t)it * KTILE;

            #pragma unroll
            for (int j = 0; j < 32; j++)    // W: rows r0+2j, 64x64 tile
                cp_async16(wd + (uint32_t)j * (2 * STRIDE * 4),
                           gw + (size_t)j * 2 * KDIM);
            #pragma unroll
            for (int j = 0; j < 16; j++)    // X: rows r0+2j, 32x64 tile
                cp_async16(xd + (uint32_t)j * (2 * STRIDE * 4),
                           gx + (size_t)j * 2 * KDIM);
            CP_COMMIT();

            if (it >= 2) {                  // signal full for tile it-2
                CP_WAIT2();
                __threadfence_block();
                if (lane == 0) MBAR_ARRIVE(barb + ((it - 2) & 3) * 16);
            }
        }
        CP_WAIT1(); __threadfence_block();
        if (lane == 0) MBAR_ARRIVE(barb + ((NKT_HALF - 2) & 3) * 16);
        CP_WAIT0(); __threadfence_block();
        if (lane == 0) MBAR_ARRIVE(barb + ((NKT_HALF - 1) & 3) * 16);
    } else {
        // ================= CONSUMERS (4 warps) =================
        const int q    = w >> 1;            // ks-half of the 64-wide tile
        const int wrow = w & 1;             // o rows [wrow*32, wrow*32+32)
        const int g = lane >> 2;
        const int c = lane & 3;
        const int r0 = wrow * 32 + g;

        #pragma unroll 1
        for (int it = 0; it < NKT_HALF; it++) {
            const int s  = it & 3;
            const int ph = (it >> 2) & 1;
            MBAR_WAIT(barb + s * 16, ph);

            const float sc = S[(size_t)srow * NSC + ((kt0 + it) >> 1)];
            const float*    wstage = wbuf + s * W_STAGE_F;
            const uint32_t* xstage = xbuf + s * X_STAGE_F;

            #pragma unroll
            for (int ks = 0; ks < 4; ks++) {
                const int k0 = q * 32 + ks * 8;

                uint32_t a[2][4];
                #pragma unroll
                for (int b = 0; b < 2; b++) {
                    const int r = r0 + b * 16;
                    a[b][0] = tf32r(sc * wstage[ r      * STRIDE + k0 + c    ]);
                    a[b][1] = tf32r(sc * wstage[(r + 8) * STRIDE + k0 + c    ]);
                    a[b][2] = tf32r(sc * wstage[ r      * STRIDE + k0 + c + 4]);
                    a[b][3] = tf32r(sc * wstage[(r + 8) * STRIDE + k0 + c + 4]);
                }

                #pragma unroll
                for (int mt = 0; mt < 4; mt++) {
                    uint32_t b0 = xstage[(mt * 8 + g) * STRIDE + k0 + c];
                    uint32_t b1 = xstage[(mt * 8 + g) * STRIDE + k0 + 4 + c];
                    MMA_TF32(acc[0][mt], a[0][0], a[0][1], a[0][2], a[0][3], b0, b1);
                    MMA_TF32(acc[1][mt], a[1][0], a[1][1], a[1][2], a[1][3], b0, b1);
                }
            }

            if (lane == 0) MBAR_ARRIVE(barb + s * 16 + 8);   // stage free
        }
    }

    // ---- epilogue: reduce 2 ks-halves, publish partial, last arriver combines ----
    __syncthreads();                                 // producer joins; ring retired
    float4* red = reinterpret_cast<float4*>(wbuf);   // 8 KB scratch
    {
        const int q    = w >> 1;
        const int wrow = w & 1;
        const int g = lane >> 2;
        const int c = lane & 3;

        if (w < 4 && q == 1) {
            #pragma unroll
            for (int b = 0; b < 2; b++)
                #pragma unroll
                for (int mt = 0; mt < 4; mt++)
                    red[((wrow * 2 + b) * 4 + mt) * 32 + lane] =
                        make_float4(acc[b][mt][0], acc[b][mt][1], acc[b][mt][2], acc[b][mt][3]);
        }
        __syncthreads();

        if (w < 4 && q == 0) {
            float* part = g_part + (size_t)kh * MDIM * ODIM;
            #pragma unroll
            for (int b = 0; b < 2; b++) {
                const int o0 = o_base + wrow * 32 + b * 16 + g;
                #pragma unroll
                for (int mt = 0; mt < 4; mt++) {
                    float4 v = red[((wrow * 2 + b) * 4 + mt) * 32 + lane];
                    const int m0 = mt * 8 + c * 2;
                    part[(size_t)m0       * ODIM + o0    ] = acc[b][mt][0] + v.x;
                    part[(size_t)(m0 + 1) * ODIM + o0    ] = acc[b][mt][1] + v.y;
                    part[(size_t)m0       * ODIM + o0 + 8] = acc[b][mt][2] + v.z;
                    part[(size_t)(m0 + 1) * ODIM + o0 + 8] = acc[b][mt][3] + v.w;
                }
            }
        }
        __threadfence();          // partial visible before taking the ticket
        __syncthreads();

        if (tid == 0) sflag[0] = atomicAdd(&g_ticket[ob], 1);
        __syncthreads();

        if (sflag[0] == 1) {      // last arriver of the pair: combine both partials
            __threadfence();      // order partial reads after ticket observation
            const float* p0 = g_part;
            const float* p1 = g_part + (size_t)MDIM * ODIM;
            // whole CTA (160 threads) combines this o-block's 32x64 output slice
            for (int i = tid; i < MDIM * OTILE; i += NTHREADS) {
                const int m = i >> 6;            // 0..31
                const int o = o_base + (i & 63);
                const size_t idx = (size_t)m * ODIM + o;
                out[idx] = ldcg(p0 + idx) + ldcg(p1 + idx);
            }
            __syncthreads();
            if (tid == 0) g_ticket[ob] = 0;      // reset for next graph replay
        }
    }
}

extern "C" void kernel_launch(void* const* d_in, const int* in_sizes, int n_in,
                              void* d_out, int out_size) {
    const float* x = (const float*)d_in[0];
    const float* w = (const float*)d_in[1];
    const float* s = (const float*)d_in[2];
    float* out = (float*)d_out;

    round_x_kernel<<<(MDIM * KDIM + 511) / 512, 512>>>(x);

    cudaFuncSetAttribute(linear_tf32_mma,
                         cudaFuncAttributeMaxDynamicSharedMemorySize, SMEM_BYTES);
    linear_tf32_mma<<<(ODIM / OTILE) * KSPLIT, NTHREADS, SMEM_BYTES>>>(w, s, out);
}

// round 16
// speedup vs baseline: 1.1015x; 1.1015x over previous
#include <cuda_runtime.h>
#include <cstdint>

#define KDIM 7168
#define ODIM 16384
#define MDIM 32
#define OTILE 64
#define KTILE 64
#define NKT_TOTAL (KDIM / KTILE)       /* 112 */
#define KSPLIT 2
#define NKT_HALF (NKT_TOTAL / KSPLIT)  /* 56 tiles per CTA */
#define NSC  56                 /* scale cols (128-wide k blocks) */
#define NTHREADS 160            /* warps 0-3 consumers, warp 4 producer */
#define STRIDE 68               /* 64+4 pad; conflict-free fragment LDS */
#define W_STAGE_F (OTILE * STRIDE)   /* 4352 floats = 17,408 B */
#define X_STAGE_F (MDIM * STRIDE)    /* 2176 floats =  8,704 B */
#define NSTAGE 3

#define RING_BYTES (NSTAGE * (W_STAGE_F + X_STAGE_F) * 4)   /* 78,336 */
#define SMEM_BYTES (RING_BYTES + 64)                        /* + mbarriers */

__device__ float g_part[KSPLIT * MDIM * ODIM];       // k-split partials (4 MB)

__device__ __forceinline__ uint32_t smem_u32(const void* p) {
    uint32_t a;
    asm("{ .reg .u64 t; cvta.to.shared.u64 t, %1; cvt.u32.u64 %0, t; }" : "=r"(a) : "l"(p));
    return a;
}

__device__ __forceinline__ uint32_t tf32r(float v) { // fp32 -> tf32 round-to-nearest
    uint32_t u;
    asm("cvt.rna.tf32.f32 %0, %1;" : "=r"(u) : "f"(v));
    return u;
}

__device__ __forceinline__ void cp_async16(uint32_t dst_smem, const void* src) {
    asm volatile("cp.async.cg.shared.global [%0], [%1], 16;" :: "r"(dst_smem), "l"(src) : "memory");
}
#define CP_COMMIT() asm volatile("cp.async.commit_group;" ::: "memory")
#define CP_WAIT2()  asm volatile("cp.async.wait_group 2;" ::: "memory")
#define CP_WAIT1()  asm volatile("cp.async.wait_group 1;" ::: "memory")
#define CP_WAIT0()  asm volatile("cp.async.wait_group 0;" ::: "memory")

#define MBAR_INIT(addr, cnt) \
    asm volatile("mbarrier.init.shared.b64 [%0], %1;" :: "r"((uint32_t)(addr)), "r"((uint32_t)(cnt)) : "memory")
#define MBAR_ARRIVE(addr) \
    asm volatile("mbarrier.arrive.shared.b64 _, [%0];" :: "r"((uint32_t)(addr)) : "memory")

#define MBAR_WAIT(mbar_addr, phase_parity) do {                                              \
    uint32_t _mbar = (uint32_t)(mbar_addr);                                                  \
    uint32_t _par  = (uint32_t)(phase_parity);                                               \
    uint32_t _done;                                                                          \
    asm volatile("{\n\t.reg .pred p;\n\t"                                                    \
        "mbarrier.try_wait.parity.acquire.cta.shared::cta.b64 p, [%1], %2;\n\t"              \
        "selp.b32 %0, 1, 0, p;\n\t}"                                                         \
        : "=r"(_done) : "r"(_mbar), "r"(_par) : "memory");                                   \
    if (!_done) {                                                                            \
        asm volatile("{\n\t.reg .pred P1;\n\t"                                               \
            "WAIT_LOOP_%=:\n\t"                                                              \
            "mbarrier.try_wait.parity.acquire.cta.shared::cta.b64 P1, [%0], %1, 0x989680;\n\t" \
            "@P1 bra.uni WAIT_DONE_%=;\n\t"                                                  \
            "bra.uni WAIT_LOOP_%=;\n\t"                                                      \
            "WAIT_DONE_%=:\n\t}"                                                             \
            :: "r"(_mbar), "r"(_par) : "memory");                                            \
    }                                                                                        \
} while (0)

#define MMA_TF32(acc, a0, a1, a2, a3, b0, b1)                                  \
    asm volatile(                                                              \
        "mma.sync.aligned.m16n8k8.row.col.f32.tf32.tf32.f32 "                  \
        "{%0,%1,%2,%3}, {%4,%5,%6,%7}, {%8,%9}, {%0,%1,%2,%3};"                \
        : "+f"((acc)[0]), "+f"((acc)[1]), "+f"((acc)[2]), "+f"((acc)[3])       \
        : "r"(a0), "r"(a1), "r"(a2), "r"(a3), "r"(b0), "r"(b1))

// ---- epilogue: sum the two k-half partials (exact-sized, 1 float4-pair/thread) ----
__global__ void reduce_kernel(float* __restrict__ out) {
    const int i = blockIdx.x * blockDim.x + threadIdx.x;        // < 131072
    const float4* p = reinterpret_cast<const float4*>(g_part);
    float4 a = p[i];
    float4 b = p[i + (MDIM * ODIM) / 4];
    reinterpret_cast<float4*>(out)[i] =
        make_float4(a.x + b.x, a.y + b.y, a.z + b.z, a.w + b.w);
}

__global__ __launch_bounds__(NTHREADS, 2)
void linear_tf32_mma(const float* __restrict__ X, const float* __restrict__ W,
                     const float* __restrict__ S)
{
    extern __shared__ float smem[];
    float*    wbuf = smem;                                   // 3 W stages
    uint32_t* xbuf = reinterpret_cast<uint32_t*>(smem + NSTAGE * W_STAGE_F);

    const int tid  = threadIdx.x;
    const int lane = tid & 31;
    const int w    = tid >> 5;          // 0..4
    const int ob   = blockIdx.x >> 1;   // o-block (0..255)
    const int kh   = blockIdx.x & 1;    // k-half (0,1)
    const int o_base = ob * OTILE;
    const int srow = ob >> 1;           // scale blocks are 128 o-rows
    const int kt0  = kh * NKT_HALF;

    const uint32_t sbase = smem_u32(smem);
    const uint32_t wsm   = sbase;
    const uint32_t xsm   = sbase + NSTAGE * W_STAGE_F * 4;
    const uint32_t barb  = sbase + RING_BYTES;   // full[s] @ s*16, empty[s] @ s*16+8

    if (tid == 0) {
        #pragma unroll
        for (int s = 0; s < NSTAGE; s++) {
            MBAR_INIT(barb + s * 16,     1);   // full: 1 producer arrival
            MBAR_INIT(barb + s * 16 + 8, 4);   // empty: 4 consumer-warp arrivals
        }
    }
    __syncthreads();

    float acc[2][4][4];
    #pragma unroll
    for (int b = 0; b < 2; b++)
        #pragma unroll
        for (int i = 0; i < 4; i++)
            #pragma unroll
            for (int j = 0; j < 4; j++) acc[b][i][j] = 0.0f;

    if (w == 4) {
        // ================= PRODUCER =================
        const int r0  = lane >> 4;      // 0 or 1
        const int col = lane & 15;
        const float* gwb = W + (size_t)o_base * KDIM + (size_t)kt0 * KTILE
                             + (size_t)r0 * KDIM + (size_t)col * 4;
        const float* gxb = X + (size_t)kt0 * KTILE
                             + (size_t)r0 * KDIM + (size_t)col * 4;
        const uint32_t soff = (uint32_t)(r0 * STRIDE + col * 4) * 4u;

        #pragma unroll 1
        for (int it = 0; it < NKT_HALF; it++) {
            const int s = it % 3;
            const int eph = (((it / 3) & 1) ^ 1);   // producer empty-phase starts at 1
            MBAR_WAIT(barb + s * 16 + 8, eph);

            const uint32_t wd = wsm + (uint32_t)s * (W_STAGE_F * 4) + soff;
            const uint32_t xd = xsm + (uint32_t)s * (X_STAGE_F * 4) + soff;
            const float* gw = gwb + (size_t)it * KTILE;
            const float* gx = gxb + (size_t)it * KTILE;

            #pragma unroll
            for (int j = 0; j < 32; j++)    // W: rows r0+2j, 64x64 tile
                cp_async16(wd + (uint32_t)j * (2 * STRIDE * 4),
                           gw + (size_t)j * 2 * KDIM);
            #pragma unroll
            for (int j = 0; j < 16; j++)    // X: rows r0+2j, 32x64 tile (raw fp32)
                cp_async16(xd + (uint32_t)j * (2 * STRIDE * 4),
                           gx + (size_t)j * 2 * KDIM);
            CP_COMMIT();

            if (it >= 2) {                  // signal full for tile it-2
                CP_WAIT2();
                __threadfence_block();
                if (lane == 0) MBAR_ARRIVE(barb + ((it - 2) % 3) * 16);
            }
        }
        CP_WAIT1(); __threadfence_block();
        if (lane == 0) MBAR_ARRIVE(barb + ((NKT_HALF - 2) % 3) * 16);
        CP_WAIT0(); __threadfence_block();
        if (lane == 0) MBAR_ARRIVE(barb + ((NKT_HALF - 1) % 3) * 16);
    } else {
        // ================= CONSUMERS (4 warps) =================
        const int q    = w >> 1;            // ks-half of the 64-wide tile
        const int wrow = w & 1;             // o rows [wrow*32, wrow*32+32)
        const int g = lane >> 2;
        const int c = lane & 3;
        const int r0 = wrow * 32 + g;

        #pragma unroll 1
        for (int it = 0; it < NKT_HALF; it++) {
            const int s  = it % 3;
            const int ph = (it / 3) & 1;
            MBAR_WAIT(barb + s * 16, ph);

            const float sc = S[(size_t)srow * NSC + ((kt0 + it) >> 1)];
            const float*    wstage = wbuf + s * W_STAGE_F;
            const uint32_t* xstage = xbuf + s * X_STAGE_F;

            #pragma unroll
            for (int ks = 0; ks < 4; ks++) {
                const int k0 = q * 32 + ks * 8;

                uint32_t a[2][4];
                #pragma unroll
                for (int b = 0; b < 2; b++) {
                    const int r = r0 + b * 16;
                    a[b][0] = tf32r(sc * wstage[ r      * STRIDE + k0 + c    ]);
                    a[b][1] = tf32r(sc * wstage[(r + 8) * STRIDE + k0 + c    ]);
                    a[b][2] = tf32r(sc * wstage[ r      * STRIDE + k0 + c + 4]);
                    a[b][3] = tf32r(sc * wstage[(r + 8) * STRIDE + k0 + c + 4]);
                }

                #pragma unroll
                for (int mt = 0; mt < 4; mt++) {
                    // raw fp32 bits: HMMA tf32 datapath reads upper 19 bits (implicit RZ)
                    uint32_t b0 = xstage[(mt * 8 + g) * STRIDE + k0 + c];
                    uint32_t b1 = xstage[(mt * 8 + g) * STRIDE + k0 + 4 + c];
                    MMA_TF32(acc[0][mt], a[0][0], a[0][1], a[0][2], a[0][3], b0, b1);
                    MMA_TF32(acc[1][mt], a[1][0], a[1][1], a[1][2], a[1][3], b0, b1);
                }
            }

            if (lane == 0) MBAR_ARRIVE(barb + s * 16 + 8);   // stage free
        }
    }

    // ---- epilogue: reduce the 2 ks-halves, write k-half partial ----
    __syncthreads();                                 // producer joins; ring retired
    float4* red = reinterpret_cast<float4*>(wbuf);   // 8 KB scratch
    if (w < 4) {
        const int q    = w >> 1;
        const int wrow = w & 1;
        const int g = lane >> 2;
        const int c = lane & 3;

        if (q == 1) {
            #pragma unroll
            for (int b = 0; b < 2; b++)
                #pragma unroll
                for (int mt = 0; mt < 4; mt++)
                    red[((wrow * 2 + b) * 4 + mt) * 32 + lane] =
                        make_float4(acc[b][mt][0], acc[b][mt][1], acc[b][mt][2], acc[b][mt][3]);
        }
        __syncthreads();

        if (q == 0) {
            float* part = g_part + (size_t)kh * MDIM * ODIM;
            #pragma unroll
            for (int b = 0; b < 2; b++) {
                const int o0 = o_base + wrow * 32 + b * 16 + g;
                #pragma unroll
                for (int mt = 0; mt < 4; mt++) {
                    float4 v = red[((wrow * 2 + b) * 4 + mt) * 32 + lane];
                    const int m0 = mt * 8 + c * 2;
                    part[(size_t)m0       * ODIM + o0    ] = acc[b][mt][0] + v.x;
                    part[(size_t)(m0 + 1) * ODIM + o0    ] = acc[b][mt][1] + v.y;
                    part[(size_t)m0       * ODIM + o0 + 8] = acc[b][mt][2] + v.z;
                    part[(size_t)(m0 + 1) * ODIM + o0 + 8] = acc[b][mt][3] + v.w;
                }
            }
        }
    } else {
        __syncthreads();    // producer matches the consumers' second barrier
    }
}

extern "C" void kernel_launch(void* const* d_in, const int* in_sizes, int n_in,
                              void* d_out, int out_size) {
    const float* x = (const float*)d_in[0];
    const float* w = (const float*)d_in[1];
    const float* s = (const float*)d_in[2];
    float* out = (float*)d_out;

    cudaFuncSetAttribute(linear_tf32_mma,
                         cudaFuncAttributeMaxDynamicSharedMemorySize, SMEM_BYTES);
    linear_tf32_mma<<<(ODIM / OTILE) * KSPLIT, NTHREADS, SMEM_BYTES>>>(x, w, s);

    reduce_kernel<<<(MDIM * ODIM / 4) / 512, 512>>>(out);
}

// round 17
// speedup vs baseline: 1.1164x; 1.0135x over previous
#include <cuda_runtime.h>
#include <cstdint>

#define KDIM 7168
#define ODIM 16384
#define MDIM 32
#define OTILE 64
#define KTILE 64
#define NKT_TOTAL (KDIM / KTILE)       /* 112 */
#define KSPLIT 2
#define NKT_HALF (NKT_TOTAL / KSPLIT)  /* 56 tiles per CTA */
#define NSC  56                 /* scale cols (128-wide k blocks) */
#define NSC_HALF 28             /* scale cols per k-half */
#define NTHREADS 160            /* warps 0-3 consumers, warp 4 producer */
#define STRIDE 68               /* 64+4 pad; conflict-free fragment LDS */
#define W_STAGE_F (OTILE * STRIDE)   /* 4352 floats = 17,408 B */
#define X_STAGE_F (MDIM * STRIDE)    /* 2176 floats =  8,704 B */
#define NSTAGE 3

#define RING_BYTES (NSTAGE * (W_STAGE_F + X_STAGE_F) * 4)   /* 78,336 */
#define SBAR_OFF   RING_BYTES                               /* 6 mbarriers (96 B) */
#define SSC_OFF    (RING_BYTES + 96)                        /* 28 scales (112 B) */
#define SMEM_BYTES (SSC_OFF + NSC_HALF * 4)

__device__ float g_part[KSPLIT * MDIM * ODIM];       // k-split partials (4 MB)

__device__ __forceinline__ uint32_t smem_u32(const void* p) {
    uint32_t a;
    asm("{ .reg .u64 t; cvta.to.shared.u64 t, %1; cvt.u32.u64 %0, t; }" : "=r"(a) : "l"(p));
    return a;
}

__device__ __forceinline__ uint32_t tf32r(float v) { // fp32 -> tf32 round-to-nearest
    uint32_t u;
    asm("cvt.rna.tf32.f32 %0, %1;" : "=r"(u) : "f"(v));
    return u;
}

__device__ __forceinline__ void cp_async16(uint32_t dst_smem, const void* src) {
    asm volatile("cp.async.cg.shared.global [%0], [%1], 16;" :: "r"(dst_smem), "l"(src) : "memory");
}
#define CP_COMMIT() asm volatile("cp.async.commit_group;" ::: "memory")
#define CP_WAIT2()  asm volatile("cp.async.wait_group 2;" ::: "memory")
#define CP_WAIT1()  asm volatile("cp.async.wait_group 1;" ::: "memory")
#define CP_WAIT0()  asm volatile("cp.async.wait_group 0;" ::: "memory")

#define MBAR_INIT(addr, cnt) \
    asm volatile("mbarrier.init.shared.b64 [%0], %1;" :: "r"((uint32_t)(addr)), "r"((uint32_t)(cnt)) : "memory")
#define MBAR_ARRIVE(addr) \
    asm volatile("mbarrier.arrive.shared.b64 _, [%0];" :: "r"((uint32_t)(addr)) : "memory")

#define MBAR_WAIT(mbar_addr, phase_parity) do {                                              \
    uint32_t _mbar = (uint32_t)(mbar_addr);                                                  \
    uint32_t _par  = (uint32_t)(phase_parity);                                               \
    uint32_t _done;                                                                          \
    asm volatile("{\n\t.reg .pred p;\n\t"                                                    \
        "mbarrier.try_wait.parity.acquire.cta.shared::cta.b64 p, [%1], %2;\n\t"              \
        "selp.b32 %0, 1, 0, p;\n\t}"                                                         \
        : "=r"(_done) : "r"(_mbar), "r"(_par) : "memory");                                   \
    if (!_done) {                                                                            \
        asm volatile("{\n\t.reg .pred P1;\n\t"                                               \
            "WAIT_LOOP_%=:\n\t"                                                              \
            "mbarrier.try_wait.parity.acquire.cta.shared::cta.b64 P1, [%0], %1, 0x989680;\n\t" \
            "@P1 bra.uni WAIT_DONE_%=;\n\t"                                                  \
            "bra.uni WAIT_LOOP_%=;\n\t"                                                      \
            "WAIT_DONE_%=:\n\t}"                                                             \
            :: "r"(_mbar), "r"(_par) : "memory");                                            \
    }                                                                                        \
} while (0)

#define MMA_TF32(acc, a0, a1, a2, a3, b0, b1)                                  \
    asm volatile(                                                              \
        "mma.sync.aligned.m16n8k8.row.col.f32.tf32.tf32.f32 "                  \
        "{%0,%1,%2,%3}, {%4,%5,%6,%7}, {%8,%9}, {%0,%1,%2,%3};"                \
        : "+f"((acc)[0]), "+f"((acc)[1]), "+f"((acc)[2]), "+f"((acc)[3])       \
        : "r"(a0), "r"(a1), "r"(a2), "r"(a3), "r"(b0), "r"(b1))

// ---- epilogue: sum the two k-half partials ----
__global__ void reduce_kernel(float* __restrict__ out) {
    const int i = blockIdx.x * blockDim.x + threadIdx.x;        // < 131072
    const float4* p = reinterpret_cast<const float4*>(g_part);
    float4 a = p[i];
    float4 b = p[i + (MDIM * ODIM) / 4];
    reinterpret_cast<float4*>(out)[i] =
        make_float4(a.x + b.x, a.y + b.y, a.z + b.z, a.w + b.w);
}

__global__ __launch_bounds__(NTHREADS, 2)
void linear_tf32_mma(const float* __restrict__ X, const float* __restrict__ W,
                     const float* __restrict__ S)
{
    extern __shared__ float smem[];
    float*    wbuf = smem;                                   // 3 W stages
    uint32_t* xbuf = reinterpret_cast<uint32_t*>(smem + NSTAGE * W_STAGE_F);
    float*    sS   = reinterpret_cast<float*>(reinterpret_cast<char*>(smem) + SSC_OFF);

    const int tid  = threadIdx.x;
    const int lane = tid & 31;
    const int w    = tid >> 5;          // 0..4
    const int ob   = blockIdx.x >> 1;   // o-block (0..255)
    const int kh   = blockIdx.x & 1;    // k-half (0,1)
    const int o_base = ob * OTILE;
    const int srow = ob >> 1;           // scale blocks are 128 o-rows
    const int kt0  = kh * NKT_HALF;

    const uint32_t sbase = smem_u32(smem);
    const uint32_t wsm   = sbase;
    const uint32_t xsm   = sbase + NSTAGE * W_STAGE_F * 4;
    const uint32_t barb  = sbase + SBAR_OFF;     // full[s] @ s*16, empty[s] @ s*16+8

    if (tid == 0) {
        #pragma unroll
        for (int s = 0; s < NSTAGE; s++) {
            MBAR_INIT(barb + s * 16,     1);   // full: 1 producer arrival
            MBAR_INIT(barb + s * 16 + 8, 4);   // empty: 4 consumer-warp arrivals
        }
    }
    // stage this CTA's 28 scales into smem (off the per-tile critical path)
    if (tid < NSC_HALF)
        sS[tid] = S[(size_t)srow * NSC + kh * NSC_HALF + tid];
    __syncthreads();

    float acc[2][4][4];
    #pragma unroll
    for (int b = 0; b < 2; b++)
        #pragma unroll
        for (int i = 0; i < 4; i++)
            #pragma unroll
            for (int j = 0; j < 4; j++) acc[b][i][j] = 0.0f;

    if (w == 4) {
        // ================= PRODUCER =================
        const int r0  = lane >> 4;      // 0 or 1
        const int col = lane & 15;
        const float* gwb = W + (size_t)o_base * KDIM + (size_t)kt0 * KTILE
                             + (size_t)r0 * KDIM + (size_t)col * 4;
        const float* gxb = X + (size_t)kt0 * KTILE
                             + (size_t)r0 * KDIM + (size_t)col * 4;
        const uint32_t soff = (uint32_t)(r0 * STRIDE + col * 4) * 4u;

        #pragma unroll 1
        for (int it = 0; it < NKT_HALF; it++) {
            const int s = it % 3;
            const int eph = (((it / 3) & 1) ^ 1);   // producer empty-phase starts at 1
            MBAR_WAIT(barb + s * 16 + 8, eph);

            const uint32_t wd = wsm + (uint32_t)s * (W_STAGE_F * 4) + soff;
            const uint32_t xd = xsm + (uint32_t)s * (X_STAGE_F * 4) + soff;
            const float* gw = gwb + (size_t)it * KTILE;
            const float* gx = gxb + (size_t)it * KTILE;

            #pragma unroll
            for (int j = 0; j < 32; j++)    // W: rows r0+2j, 64x64 tile
                cp_async16(wd + (uint32_t)j * (2 * STRIDE * 4),
                           gw + (size_t)j * 2 * KDIM);
            #pragma unroll
            for (int j = 0; j < 16; j++)    // X: rows r0+2j, 32x64 tile (raw fp32)
                cp_async16(xd + (uint32_t)j * (2 * STRIDE * 4),
                           gx + (size_t)j * 2 * KDIM);
            CP_COMMIT();

            if (it >= 2) {                  // signal full for tile it-2
                CP_WAIT2();
                __threadfence_block();
                if (lane == 0) MBAR_ARRIVE(barb + ((it - 2) % 3) * 16);
            }
        }
        CP_WAIT1(); __threadfence_block();
        if (lane == 0) MBAR_ARRIVE(barb + ((NKT_HALF - 2) % 3) * 16);
        CP_WAIT0(); __threadfence_block();
        if (lane == 0) MBAR_ARRIVE(barb + ((NKT_HALF - 1) % 3) * 16);
    } else {
        // ================= CONSUMERS (4 warps) =================
        const int q    = w >> 1;            // ks-half of the 64-wide tile
        const int wrow = w & 1;             // o rows [wrow*32, wrow*32+32)
        const int g = lane >> 2;
        const int c = lane & 3;
        const int r0 = wrow * 32 + g;

        #pragma unroll 1
        for (int it = 0; it < NKT_HALF; it++) {
            const int s  = it % 3;
            const int ph = (it / 3) & 1;
            MBAR_WAIT(barb + s * 16, ph);

            const float sc = sS[it >> 1];   // LDS, not a post-barrier L2 round-trip
            const float*    wstage = wbuf + s * W_STAGE_F;
            const uint32_t* xstage = xbuf + s * X_STAGE_F;

            #pragma unroll
            for (int ks = 0; ks < 4; ks++) {
                const int k0 = q * 32 + ks * 8;

                uint32_t a[2][4];
                #pragma unroll
                for (int b = 0; b < 2; b++) {
                    const int r = r0 + b * 16;
                    a[b][0] = tf32r(sc * wstage[ r      * STRIDE + k0 + c    ]);
                    a[b][1] = tf32r(sc * wstage[(r + 8) * STRIDE + k0 + c    ]);
                    a[b][2] = tf32r(sc * wstage[ r      * STRIDE + k0 + c + 4]);
                    a[b][3] = tf32r(sc * wstage[(r + 8) * STRIDE + k0 + c + 4]);
                }

                #pragma unroll
                for (int mt = 0; mt < 4; mt++) {
                    // raw fp32 bits: HMMA tf32 datapath reads upper 19 bits (implicit RZ)
                    uint32_t b0 = xstage[(mt * 8 + g) * STRIDE + k0 + c];
                    uint32_t b1 = xstage[(mt * 8 + g) * STRIDE + k0 + 4 + c];
                    MMA_TF32(acc[0][mt], a[0][0], a[0][1], a[0][2], a[0][3], b0, b1);
                    MMA_TF32(acc[1][mt], a[1][0], a[1][1], a[1][2], a[1][3], b0, b1);
                }
            }

            if (lane == 0) MBAR_ARRIVE(barb + s * 16 + 8);   // stage free
        }
    }

    // ---- epilogue: reduce the 2 ks-halves, write k-half partial ----
    __syncthreads();                                 // producer joins; ring retired
    float4* red = reinterpret_cast<float4*>(wbuf);   // 8 KB scratch
    if (w < 4) {
        const int q    = w >> 1;
        const int wrow = w & 1;
        const int g = lane >> 2;
        const int c = lane & 3;

        if (q == 1) {
            #pragma unroll
            for (int b = 0; b < 2; b++)
                #pragma unroll
                for (int mt = 0; mt < 4; mt++)
                    red[((wrow * 2 + b) * 4 + mt) * 32 + lane] =
                        make_float4(acc[b][mt][0], acc[b][mt][1], acc[b][mt][2], acc[b][mt][3]);
        }
        __syncthreads();

        if (q == 0) {
            float* part = g_part + (size_t)kh * MDIM * ODIM;
            #pragma unroll
            for (int b = 0; b < 2; b++) {
                const int o0 = o_base + wrow * 32 + b * 16 + g;
                #pragma unroll
                for (int mt = 0; mt < 4; mt++) {
                    float4 v = red[((wrow * 2 + b) * 4 + mt) * 32 + lane];
                    const int m0 = mt * 8 + c * 2;
                    part[(size_t)m0       * ODIM + o0    ] = acc[b][mt][0] + v.x;
                    part[(size_t)(m0 + 1) * ODIM + o0    ] = acc[b][mt][1] + v.y;
                    part[(size_t)m0       * ODIM + o0 + 8] = acc[b][mt][2] + v.z;
                    part[(size_t)(m0 + 1) * ODIM + o0 + 8] = acc[b][mt][3] + v.w;
                }
            }
        }
    } else {
        __syncthreads();    // producer matches the consumers' second barrier
    }
}

extern "C" void kernel_launch(void* const* d_in, const int* in_sizes, int n_in,
                              void* d_out, int out_size) {
    const float* x = (const float*)d_in[0];
    const float* w = (const float*)d_in[1];
    const float* s = (const float*)d_in[2];
    float* out = (float*)d_out;

    cudaFuncSetAttribute(linear_tf32_mma,
                         cudaFuncAttributeMaxDynamicSharedMemorySize, SMEM_BYTES);
    linear_tf32_mma<<<(ODIM / OTILE) * KSPLIT, NTHREADS, SMEM_BYTES>>>(x, w, s);

    reduce_kernel<<<(MDIM * ODIM / 4) / 512, 512>>>(out);
}